// round 1
// baseline (speedup 1.0000x reference)
#include <cuda_runtime.h>
#include <cstdint>

#define OUT_SEGS 100000
#define FDIM 128

// Scratch (allocation-free rule): pooled sums [OUT_SEGS, 128] + counts [OUT_SEGS]
__device__ float g_pooled[(size_t)OUT_SEGS * FDIM];
__device__ float g_count[OUT_SEGS];

// ---------------------------------------------------------------------------
// 1) zero scratch
__global__ void zero_kernel() {
    size_t total = (size_t)OUT_SEGS * FDIM;
    size_t stride = (size_t)gridDim.x * blockDim.x;
    for (size_t i = (size_t)blockIdx.x * blockDim.x + threadIdx.x; i < total; i += stride)
        g_pooled[i] = 0.0f;
    for (size_t i = (size_t)blockIdx.x * blockDim.x + threadIdx.x; i < OUT_SEGS; i += stride)
        g_count[i] = 0.0f;
}

// ---------------------------------------------------------------------------
// 2) scatter: one warp per input row. Each lane handles 4 consecutive floats
//    via a single vectorized red.global.add.v4.f32 (sm_90+).
__global__ void scatter_kernel(const float* __restrict__ x,
                               const int* __restrict__ index, int N) {
    int warp_global = (blockIdx.x * blockDim.x + threadIdx.x) >> 5;
    int lane = threadIdx.x & 31;
    int nwarps = (gridDim.x * blockDim.x) >> 5;

    for (int row = warp_global; row < N; row += nwarps) {
        int seg = index[row];
        float4 v = reinterpret_cast<const float4*>(x + (size_t)row * FDIM)[lane];
        float* dst = g_pooled + (size_t)seg * FDIM + lane * 4;
        asm volatile("red.global.add.v4.f32 [%0], {%1, %2, %3, %4};"
                     :: "l"(dst), "f"(v.x), "f"(v.y), "f"(v.z), "f"(v.w)
                     : "memory");
        if (lane == 0)
            atomicAdd(g_count + seg, 1.0f);
    }
}

// ---------------------------------------------------------------------------
// 3) finalize: pooled[seg][:] /= (count[seg] + eps), in place
__global__ void finalize_kernel() {
    size_t total = (size_t)OUT_SEGS * FDIM;
    size_t stride = (size_t)gridDim.x * blockDim.x;
    for (size_t i = (size_t)blockIdx.x * blockDim.x + threadIdx.x; i < total; i += stride) {
        int seg = (int)(i >> 7);  // i / 128
        float inv = 1.0f / (g_count[seg] + 1e-9f);
        g_pooled[i] *= inv;
    }
}

// ---------------------------------------------------------------------------
// 4) gather: one warp per output row, float4 per lane.
//    pooled is 51.2 MB -> mostly L2-resident; out store is coalesced streaming.
__global__ void gather_kernel(const int* __restrict__ index,
                              float* __restrict__ out, int N) {
    int warp_global = (blockIdx.x * blockDim.x + threadIdx.x) >> 5;
    int lane = threadIdx.x & 31;
    int nwarps = (gridDim.x * blockDim.x) >> 5;

    for (int row = warp_global; row < N; row += nwarps) {
        int seg = index[row];
        float4 v = reinterpret_cast<const float4*>(g_pooled + (size_t)seg * FDIM)[lane];
        reinterpret_cast<float4*>(out + (size_t)row * FDIM)[lane] = v;
    }
}

// ---------------------------------------------------------------------------
extern "C" void kernel_launch(void* const* d_in, const int* in_sizes, int n_in,
                              void* d_out, int out_size) {
    const float* x   = (const float*)d_in[0];
    const int* index = (const int*)d_in[1];
    float* out = (float*)d_out;

    int N = in_sizes[1];  // number of rows (index has N elements)

    // 1) zero scratch
    zero_kernel<<<1184, 256>>>();

    // 2) scatter: warp per row -> N*32 threads
    {
        int threads = 256;
        int warps_per_block = threads / 32;
        int blocks = (N + warps_per_block - 1) / warps_per_block;
        scatter_kernel<<<blocks, threads>>>(x, index, N);
    }

    // 3) finalize
    finalize_kernel<<<1184, 256>>>();

    // 4) gather
    {
        int threads = 256;
        int warps_per_block = threads / 32;
        int blocks = (N + warps_per_block - 1) / warps_per_block;
        gather_kernel<<<blocks, threads>>>(index, out, N);
    }
}

// round 3
// speedup vs baseline: 1.4104x; 1.4104x over previous
#include <cuda_runtime.h>
#include <cstdint>

#define OUT_SEGS 100000
#define FDIM 128

// Scratch (allocation-free rule): pooled sums [OUT_SEGS, 128] + counts [OUT_SEGS]
__device__ float g_pooled[(size_t)OUT_SEGS * FDIM];
__device__ float g_count[OUT_SEGS];

// ---------------------------------------------------------------------------
// 1) zero scratch
__global__ void zero_kernel() {
    size_t total = (size_t)OUT_SEGS * FDIM;
    size_t stride = (size_t)gridDim.x * blockDim.x;
    for (size_t i = (size_t)blockIdx.x * blockDim.x + threadIdx.x; i < total; i += stride)
        g_pooled[i] = 0.0f;
    for (size_t i = (size_t)blockIdx.x * blockDim.x + threadIdx.x; i < OUT_SEGS; i += stride)
        g_count[i] = 0.0f;
}

// ---------------------------------------------------------------------------
// 2) scatter: one warp per input row. Each lane handles 4 consecutive floats
//    via a single vectorized red.global.add.v4.f32 (sm_90+).
//    x is streamed once -> ld.global.cs keeps it out of L2 so the atomic
//    target lines (g_pooled) stay resident.
__global__ void scatter_kernel(const float* __restrict__ x,
                               const int* __restrict__ index, int N) {
    int warp_global = (blockIdx.x * blockDim.x + threadIdx.x) >> 5;
    int lane = threadIdx.x & 31;

    if (warp_global >= N) return;
    int row = warp_global;

    int seg = index[row];
    const float* src = x + (size_t)row * FDIM + lane * 4;
    float4 v;
    asm volatile("ld.global.cs.v4.f32 {%0, %1, %2, %3}, [%4];"
                 : "=f"(v.x), "=f"(v.y), "=f"(v.z), "=f"(v.w)
                 : "l"(src));
    float* dst = g_pooled + (size_t)seg * FDIM + lane * 4;
    asm volatile("red.global.add.v4.f32 [%0], {%1, %2, %3, %4};"
                 :: "l"(dst), "f"(v.x), "f"(v.y), "f"(v.z), "f"(v.w)
                 : "memory");
    if (lane == 0)
        atomicAdd(g_count + seg, 1.0f);
}

// ---------------------------------------------------------------------------
// 3) gather (fused finalize): one warp per output row pair, float4 per lane.
//    pooled reads: ld.global.nc.L2::cache_hint with evict_last policy
//                  (keep pooled resident in L2)
//    out writes:   st.global.cs (evict-first, don't thrash L2)
//    Scale by 1/(count+eps) on the fly -> finalize kernel eliminated.
//    2 rows per warp-iteration for MLP.
__global__ void gather_kernel(const int* __restrict__ index,
                              float* __restrict__ out, int N) {
    int warp_global = (blockIdx.x * blockDim.x + threadIdx.x) >> 5;
    int lane = threadIdx.x & 31;

    int row0 = warp_global * 2;
    int row1 = row0 + 1;
    if (row0 >= N) return;

    // evict-last cache policy for pooled reads
    uint64_t policy;
    asm volatile("createpolicy.fractional.L2::evict_last.b64 %0, 1.0;"
                 : "=l"(policy));

    int seg0 = index[row0];
    int seg1 = (row1 < N) ? index[row1] : seg0;

    const float* p0 = g_pooled + (size_t)seg0 * FDIM + lane * 4;
    const float* p1 = g_pooled + (size_t)seg1 * FDIM + lane * 4;

    float4 a, b;
    asm volatile("ld.global.nc.L2::cache_hint.v4.f32 {%0, %1, %2, %3}, [%4], %5;"
                 : "=f"(a.x), "=f"(a.y), "=f"(a.z), "=f"(a.w)
                 : "l"(p0), "l"(policy));
    asm volatile("ld.global.nc.L2::cache_hint.v4.f32 {%0, %1, %2, %3}, [%4], %5;"
                 : "=f"(b.x), "=f"(b.y), "=f"(b.z), "=f"(b.w)
                 : "l"(p1), "l"(policy));

    float c0 = __ldg(g_count + seg0);
    float c1 = __ldg(g_count + seg1);
    float inv0 = 1.0f / (c0 + 1e-9f);
    float inv1 = 1.0f / (c1 + 1e-9f);

    a.x *= inv0; a.y *= inv0; a.z *= inv0; a.w *= inv0;
    b.x *= inv1; b.y *= inv1; b.z *= inv1; b.w *= inv1;

    float* o0 = out + (size_t)row0 * FDIM + lane * 4;
    asm volatile("st.global.cs.v4.f32 [%0], {%1, %2, %3, %4};"
                 :: "l"(o0), "f"(a.x), "f"(a.y), "f"(a.z), "f"(a.w) : "memory");
    if (row1 < N) {
        float* o1 = out + (size_t)row1 * FDIM + lane * 4;
        asm volatile("st.global.cs.v4.f32 [%0], {%1, %2, %3, %4};"
                     :: "l"(o1), "f"(b.x), "f"(b.y), "f"(b.z), "f"(b.w) : "memory");
    }
}

// ---------------------------------------------------------------------------
extern "C" void kernel_launch(void* const* d_in, const int* in_sizes, int n_in,
                              void* d_out, int out_size) {
    const float* x   = (const float*)d_in[0];
    const int* index = (const int*)d_in[1];
    float* out = (float*)d_out;

    int N = in_sizes[1];  // number of rows (index has N elements)

    // 1) zero scratch
    zero_kernel<<<1184, 256>>>();

    // 2) scatter: warp per row -> N warps
    {
        int threads = 256;
        int warps_per_block = threads / 32;
        int blocks = (N + warps_per_block - 1) / warps_per_block;
        scatter_kernel<<<blocks, threads>>>(x, index, N);
    }

    // 3) gather (fused finalize): warp per 2 rows
    {
        int threads = 256;
        int rows_per_block = (threads / 32) * 2;
        int blocks = (N + rows_per_block - 1) / rows_per_block;
        gather_kernel<<<blocks, threads>>>(index, out, N);
    }
}